// round 16
// baseline (speedup 1.0000x reference)
#include <cuda_runtime.h>
#include <math.h>
#include <stdint.h>

#define BB 2
#define NN 4
#define CCH 128
#define HEADS 8
#define PP 4
#define HH 96
#define WW 96
#define TCC 64
#define NITERS 3
#define HD 16
#define HWSZ (HH*WW)   // 9216
#define BPITCH 40

// ---------------- scratch (device globals; no allocation) ----------------
__device__ float g_q   [BB*CCH*HWSZ];          // BCHW
__device__ float g_v   [BB*NN*CCH*HWSZ];       // BCHW (conv output)
__device__ float g_vp  [BB*NN*CCH*HWSZ];       // pixel-major copy [bn][h][pix][HD]
__device__ float g_tmp [BB*CCH*HWSZ];          // BCHW
__device__ float g_net [BB*HEADS*HWSZ*HD];     // pixel-head-major
__device__ float g_agg [BB*CCH*HWSZ];          // BCHW
__device__ float g_ent [BB*HEADS*HWSZ];
__device__ float g_tbias[BB*HEADS*NN];
__device__ int   g_nid [BB];
__device__ float g_wprep[5*8*4096];            // pre-split/permuted conv weights

__device__ __forceinline__ float geluf(float v){ return 0.5f*v*(1.0f+erff(v*0.70710678118654752f)); }
__device__ __forceinline__ float sigm(float v){ return 1.0f/(1.0f+expf(-v)); }
__device__ __forceinline__ float fsig(float v){ return fdividef(1.0f, 1.0f + __expf(-v)); }
__device__ __forceinline__ float ftanh(float v){ return 1.0f - fdividef(2.0f, __expf(2.0f*v) + 1.0f); }
__device__ __forceinline__ float tf32r(float x){
    uint32_t o; asm("cvt.rna.tf32.f32 %0, %1;" : "=r"(o) : "f"(x));
    return __uint_as_float(o);
}
__device__ __forceinline__ void mma8(float* c, const float* a, const float* b){
    asm volatile("mma.sync.aligned.m16n8k8.row.col.f32.tf32.tf32.f32 "
        "{%0,%1,%2,%3}, {%4,%5,%6,%7}, {%8,%9}, {%0,%1,%2,%3};"
        : "+f"(c[0]),"+f"(c[1]),"+f"(c[2]),"+f"(c[3])
        : "r"(__float_as_uint(a[0])),"r"(__float_as_uint(a[1])),
          "r"(__float_as_uint(a[2])),"r"(__float_as_uint(a[3])),
          "r"(__float_as_uint(b[0])),"r"(__float_as_uint(b[1])));
}

// ---------------- weight prep: permute + hi/lo split, once ----------------
__global__ void wprep_k(const float* __restrict__ qw, const float* __restrict__ vw,
                        const float* __restrict__ pww, const float* __restrict__ o1w,
                        const float* __restrict__ o2w)
{
    const float* ws[5] = {qw, vw, pww, o1w, o2w};
    int ck = blockIdx.x;
    int ci = blockIdx.y;
    const float* w = ws[ci];
    int tid = threadIdx.x;
    int oc  = tid >> 1;
    int klb = (tid & 1) * 8;
    const float* wp = w + (size_t)oc * CCH + ck*16 + klb;
    float4 v0 = *reinterpret_cast<const float4*>(wp);
    float4 v1 = *reinterpret_cast<const float4*>(wp + 4);
    float vv[8] = {v0.x,v0.y,v0.z,v0.w,v1.x,v1.y,v1.z,v1.w};
    int mt = oc >> 4, og = oc & 15, gi = og & 7, half = og >> 3;
    float* dst = g_wprep + ((size_t)ci*8 + ck)*4096;
    #pragma unroll
    for (int j=0;j<8;j++){
        int kl = klb + j;
        int kc = kl >> 3, kk = kl & 7;
        int tt = kk & 3, khalf = kk >> 2;
        int idx = ((mt*2+kc)*32 + gi*4 + tt)*4 + (half + 2*khalf);
        float hi = tf32r(vv[j]);
        dst[idx]        = hi;
        dst[2048 + idx] = tf32r(vv[j] - hi);
    }
}

// ---------------- v transpose: BCHW -> [bn][h][pix][HD] ----------------
__global__ __launch_bounds__(256)
void vt_k()
{
    __shared__ float tile[16][130];
    int plane = blockIdx.y;              // bn*HEADS + h
    int bn = plane / HEADS, h = plane % HEADS;
    int pix0 = blockIdx.x * 128;
    int tid = threadIdx.x;
    const float* src = g_v + ((size_t)bn*CCH + h*HD)*HWSZ + pix0;
    for (int i = tid; i < 16*128; i += 256){
        int d = i >> 7, p = i & 127;
        tile[d][p] = src[(size_t)d*HWSZ + p];
    }
    __syncthreads();
    float* dst = g_vp + ((size_t)plane*HWSZ + pix0)*HD;
    for (int i = tid; i < 16*128; i += 256){
        int pix = i >> 4, d = i & 15;
        dst[pix*HD + d] = tile[d][pix];
    }
}

// ---------------- tiny kernel: t_bias + nearest_idx ----------------
__global__ void small_k(const float* __restrict__ rel_time,
                        const float* __restrict__ time_enc,
                        const float* __restrict__ tw,
                        const float* __restrict__ tb)
{
    int t = threadIdx.x;
    if (t < BB*HEADS*NN) {
        int n = t % NN; int h = (t/NN) % HEADS; int b = t/(NN*HEADS);
        float s = tb[h];
        for (int k=0;k<TCC;k++) s += time_enc[(b*NN+n)*TCC+k]*tw[h*TCC+k];
        g_tbias[t] = s;
    } else if (t < BB*HEADS*NN + BB) {
        int b = t - BB*HEADS*NN;
        float best = fabsf(rel_time[b*NN]); int id = 0;
        for (int n=1;n<NN;n++){ float v=fabsf(rel_time[b*NN+n]); if (v<best){best=v;id=n;} }
        g_nid[b] = id;
    }
}

// ---------------- depthwise 7x7 + bias + gelu (smem tiled) ----------------
__global__ __launch_bounds__(256)
void dw_k(const float* __restrict__ q,
          const float* __restrict__ dww,
          const float* __restrict__ dwb)
{
    __shared__ float tile[38][40];
    __shared__ float wsm[49];
    int plane = blockIdx.z;
    int c = plane & (CCH-1);
    int tx0 = blockIdx.x * 32;
    int ty0 = blockIdx.y * 32;
    const float* qp = q + (size_t)plane * HWSZ;
    int tid = threadIdx.x;
    if (tid < 49) wsm[tid] = dww[c*49 + tid];
    for (int i = tid; i < 38*38; i += 256){
        int r = i / 38, cc = i - r*38;
        int gy = ty0 + r - 3, gx = tx0 + cc - 3;
        float v = 0.f;
        if (gy>=0 && gy<HH && gx>=0 && gx<WW) v = qp[gy*WW+gx];
        tile[r][cc] = v;
    }
    __syncthreads();
    float wr[49];
    #pragma unroll
    for (int i=0;i<49;i++) wr[i]=wsm[i];
    int lx = tid & 31;
    int ly0 = tid >> 5;
    float bz = dwb[c];
    float* outp = g_tmp + (size_t)plane*HWSZ;
    #pragma unroll
    for (int j=0;j<4;j++){
        int ly = ly0 + j*8;
        float acc = 0.f;
        #pragma unroll
        for (int ky=0;ky<7;ky++)
            #pragma unroll
            for (int kx=0;kx<7;kx++)
                acc += tile[ly+ky][lx+kx]*wr[ky*7+kx];
        outp[(ty0+ly)*WW + tx0+lx] = geluf(acc + bz);
    }
}

// ---------------- 3xTF32 tensor-core conv1x1 (R8-exact) ----------------
__global__ __launch_bounds__(256, 2)
void conv1x1_mma_k(const float* __restrict__ in, const float* __restrict__ wA,
                   const float* __restrict__ bias, float* __restrict__ out,
                   int act, int layout, const float* __restrict__ gate)
{
    __shared__ float sA[4096];
    __shared__ float sB[2][16*132];
    const int tid  = threadIdx.x;
    const int lane = tid & 31;
    const int warp = tid >> 5;
    const int g  = lane >> 2;
    const int t4 = lane & 3;

    const int pix0 = blockIdx.x * 128;
    const int img  = blockIdx.y;
    const float* inb = in + (size_t)img * CCH * HWSZ;

    const int wOc  = (warp & 1) * 64;
    const int wPix = (warp >> 1) * 32;

    float c[4][4][4];
    #pragma unroll
    for (int i=0;i<4;i++)
        #pragma unroll
        for (int j=0;j<4;j++)
            #pragma unroll
            for (int r=0;r<4;r++) c[i][j][r]=0.f;

    for (int k0 = 0; k0 < CCH; k0 += 16) {
        {
            const float4* src = reinterpret_cast<const float4*>(wA + (size_t)(k0>>4)*4096);
            float4* dA = reinterpret_cast<float4*>(sA);
            dA[tid]       = src[tid];
            dA[tid + 256] = src[tid + 256];
            dA[tid + 512] = src[tid + 512];
            dA[tid + 768] = src[tid + 768];
        }
        {
            int kl = tid >> 4;
            int px = (tid & 15) * 8;
            const float* ip = inb + (size_t)(k0+kl)*HWSZ + pix0 + px;
            float4 v0 = *reinterpret_cast<const float4*>(ip);
            float4 v1 = *reinterpret_cast<const float4*>(ip+4);
            float vv[8] = {v0.x,v0.y,v0.z,v0.w,v1.x,v1.y,v1.z,v1.w};
            int base = kl*132 + px;
            #pragma unroll
            for (int j=0;j<8;j++){
                float hi = tf32r(vv[j]);
                sB[0][base+j] = hi;
                sB[1][base+j] = tf32r(vv[j] - hi);
            }
        }
        __syncthreads();
        #pragma unroll
        for (int kc=0; kc<2; kc++){
            float ah[4][4], al[4][4];
            #pragma unroll
            for (int mt=0; mt<4; mt++){
                int mtg = (wOc>>4) + mt;
                int idx = ((mtg*2+kc)*32+lane)*4;
                float4 avh = *reinterpret_cast<const float4*>(&sA[idx]);
                float4 avl = *reinterpret_cast<const float4*>(&sA[2048+idx]);
                ah[mt][0]=avh.x; ah[mt][1]=avh.y; ah[mt][2]=avh.z; ah[mt][3]=avh.w;
                al[mt][0]=avl.x; al[mt][1]=avl.y; al[mt][2]=avl.z; al[mt][3]=avl.w;
            }
            float bh[4][2], bl[4][2];
            #pragma unroll
            for (int nt=0; nt<4; nt++){
                int px = wPix + nt*8 + g;
                int i0 = (kc*8+t4)*132 + px;
                int i1 = (kc*8+t4+4)*132 + px;
                bh[nt][0] = sB[0][i0];  bh[nt][1] = sB[0][i1];
                bl[nt][0] = sB[1][i0];  bl[nt][1] = sB[1][i1];
            }
            #pragma unroll
            for (int mt=0; mt<4; mt++)
                #pragma unroll
                for (int nt=0; nt<4; nt++){
                    mma8(c[mt][nt], ah[mt], bl[nt]);
                    mma8(c[mt][nt], al[mt], bh[nt]);
                    mma8(c[mt][nt], ah[mt], bh[nt]);
                }
        }
        __syncthreads();
    }

    #pragma unroll
    for (int mt=0; mt<4; mt++){
        int oc1 = wOc + mt*16 + g;
        int oc2 = oc1 + 8;
        float b1 = bias[oc1], b2 = bias[oc2];
        float m1 = 1.f, m2 = 1.f;
        if (act==2){ m1 = sigm(gate[oc1]); m2 = sigm(gate[oc2]); }
        #pragma unroll
        for (int nt=0; nt<4; nt++){
            int p = pix0 + wPix + nt*8 + t4*2;
            float v0 = c[mt][nt][0] + b1, v1 = c[mt][nt][1] + b1;
            float v2 = c[mt][nt][2] + b2, v3 = c[mt][nt][3] + b2;
            if (act==1){ v0=geluf(v0); v1=geluf(v1); v2=geluf(v2); v3=geluf(v3); }
            else if (act==2){ v0*=m1; v1*=m1; v2*=m2; v3*=m2; }
            if (layout==0){
                float2* o1 = reinterpret_cast<float2*>(out + (size_t)img*CCH*HWSZ + (size_t)oc1*HWSZ + p);
                float2* o2 = reinterpret_cast<float2*>(out + (size_t)img*CCH*HWSZ + (size_t)oc2*HWSZ + p);
                *o1 = make_float2(v0, v1);
                *o2 = make_float2(v2, v3);
            } else {
                out[(((size_t)img*HEADS + (oc1>>4))*HWSZ + p  )*HD + (oc1&15)] = v0;
                out[(((size_t)img*HEADS + (oc1>>4))*HWSZ + p+1)*HD + (oc1&15)] = v1;
                out[(((size_t)img*HEADS + (oc2>>4))*HWSZ + p  )*HD + (oc2&15)] = v2;
                out[(((size_t)img*HEADS + (oc2>>4))*HWSZ + p+1)*HD + (oc2&15)] = v3;
            }
        }
    }
}

// ---------------- fused: correlation + MMA-GRU + softmax + final gather ----------------
// gathers read pixel-major g_vp with float4
#define FK_SMEM_FLOATS 21104
__global__ __launch_bounds__(128)
void fused_k(const float* __restrict__ wih, const float* __restrict__ whh,
             const float* __restrict__ bih, const float* __restrict__ bhh,
             const float* __restrict__ offw, const float* __restrict__ offb,
             const float* __restrict__ aw,  const float* __restrict__ ab)
{
    extern __shared__ float sm[];
    float* s_wih = sm;
    float* s_whh = sm+864;
    float* s_bsum= sm+1632;
    float* s_bihn= sm+1664;
    float* s_bhhn= sm+1680;
    float* s_offw= sm+1696;
    float* s_aw  = sm+1824;
    float* s_offb= sm+1888;
    float* s_ab  = sm+1896;
    float* aF_h  = sm+1904;
    float* aF_l  = sm+3824;
    float* s_bhA = sm+5744;
    float* s_blA = sm+12144;
    float* s_nA  = sm+18544;

    int t = threadIdx.x;
    int lane = t & 31, warp = t >> 5;
    int g = lane >> 2, t4 = lane & 3;

    for (int i=t;i<864;i+=128) s_wih[i]=wih[i];
    for (int i=t;i<768;i+=128) s_whh[i]=whh[i];
    if (t<32) s_bsum[t]=bih[t]+bhh[t];
    else if (t<48){ s_bihn[t-32]=bih[t]; s_bhhn[t-32]=bhh[t]; }
    s_offw[t] = offw[t];
    if (t<64) s_aw[t] = aw[t];
    if (t>=64 && t<72) s_offb[t-64]=offb[t-64];
    if (t>=72 && t<76) s_ab[t-72]=ab[t-72];
    __syncthreads();

    for (int tt=warp; tt<15; tt+=4){
        int kt = tt/3, mt = tt - kt*3;
        #pragma unroll
        for (int idx=0; idx<4; idx++){
            int row = g + ((idx & 1) << 3);
            int col = kt*8 + t4 + ((idx >> 1) << 2);
            float e;
            if (mt < 2){
                int j = mt*16 + row;
                e = (col < 18) ? s_wih[j*18+col] : ((col < 24) ? 0.f : s_whh[j*16 + col-24]);
            } else if (kt < 3){
                e = (col < 18) ? s_wih[(32+row)*18 + col] : 0.f;
            } else {
                e = s_whh[(32+row)*16 + (col-24)];
            }
            float h = tf32r(e);
            aF_h[(tt*32+lane)*4+idx] = h;
            aF_l[(tt*32+lane)*4+idx] = tf32r(e - h);
        }
    }

    float* bhb = s_bhA + warp*1600;
    float* blb = s_blA + warp*1600;
    float* s_nw = s_nA + warp*640;
    for (int i=lane; i<6*BPITCH; i+=32){ bhb[18*BPITCH+i]=0.f; blb[18*BPITCH+i]=0.f; }
    __syncthreads();

    int ph  = blockIdx.x*128 + t;
    int pix = ph % HWSZ;
    int bh_ = ph / HWSZ;
    int h   = bh_ % HEADS;
    int b   = bh_ / HEADS;
    int x   = pix % WW, y = pix / WW;
    float bx = -1.f + x*(2.f/(WW-1));
    float by = -1.f + y*(2.f/(HH-1));

    const float* vnear = g_vp + ((size_t)(b*NN + g_nid[b])*HEADS + h)*HWSZ*HD;
    const float* qbase = g_q + ((size_t)b*CCH + h*HD)*HWSZ + pix;

    float qv[HD];
    #pragma unroll
    for (int d=0;d<HD;d++) qv[d] = qbase[(size_t)d*HWSZ];
    const int sdx[5] = {0,-1,1,0,0};
    const int sdy[5] = {0,0,0,-1,1};
    float bestsc = 0.f; int bi = 0;
    #pragma unroll
    for (int s=0;s<5;s++){
        int sy = y - sdy[s], sx = x - sdx[s];
        float sc = 0.f;
        if (sy>=0 && sy<HH && sx>=0 && sx<WW){
            const float4* vp = reinterpret_cast<const float4*>(vnear + (size_t)(sy*WW+sx)*HD);
            #pragma unroll
            for (int d4=0;d4<4;d4++){
                float4 vv = vp[d4];
                sc += qv[4*d4  ]*vv.x;
                sc += qv[4*d4+1]*vv.y;
                sc += qv[4*d4+2]*vv.z;
                sc += qv[4*d4+3]*vv.w;
            }
        }
        if (s==0 || sc > bestsc){ bestsc = sc; bi = s; }
    }
    float ox0 = sdy[bi]*(2.f/WW);
    float oy0 = sdx[bi]*(2.f/HH);

    float offs[PP*2];
    #pragma unroll
    for (int p=0;p<PP;p++){ offs[2*p]=ox0; offs[2*p+1]=oy0; }
    float attn[PP] = {0.f,0.f,0.f,0.f};

    {
        const float4* np4 = reinterpret_cast<const float4*>(g_net + (size_t)ph*HD);
        #pragma unroll
        for (int d4=0; d4<4; d4++){
            float4 v = np4[d4];
            float vv[4] = {v.x,v.y,v.z,v.w};
            #pragma unroll
            for (int j=0;j<4;j++){
                int d = d4*4+j;
                s_nw[d*BPITCH+lane] = vv[j];
                float hh = tf32r(vv[j]);
                bhb[(24+d)*BPITCH+lane] = hh;
                blb[(24+d)*BPITCH+lane] = tf32r(vv[j]-hh);
            }
        }
    }
    __syncwarp();
    float net_c[4][4];
    #pragma unroll
    for (int nt=0; nt<4; nt++)
        #pragma unroll
        for (int idx=0; idx<4; idx++){
            int row = g + ((idx>>1)<<3);
            int col = nt*8 + 2*t4 + (idx&1);
            net_c[nt][idx] = s_nw[row*BPITCH+col];
        }

    for (int it=0; it<NITERS; it++){
        float p0x = offs[0], p0y = offs[1];
        float sgx = fminf(fmaxf(bx+p0x,-1.f),1.f);
        float sgy = fminf(fmaxf(by+p0y,-1.f),1.f);
        float ixf = (sgx+1.f)*0.5f*(WW-1);
        float iyf = (sgy+1.f)*0.5f*(HH-1);
        float x0f = floorf(ixf), y0f = floorf(iyf);
        float wx = ixf-x0f, wy = iyf-y0f;
        int x0 = min(max((int)x0f,0),WW-1);
        int x1 = min(max((int)x0f+1,0),WW-1);
        int y0 = min(max((int)y0f,0),HH-1);
        int y1 = min(max((int)y0f+1,0),HH-1);
        float w00=(1.f-wx)*(1.f-wy), w01=wx*(1.f-wy), w10=(1.f-wx)*wy, w11=wx*wy;
        const float4* p00 = reinterpret_cast<const float4*>(vnear + (size_t)(y0*WW+x0)*HD);
        const float4* p01 = reinterpret_cast<const float4*>(vnear + (size_t)(y0*WW+x1)*HD);
        const float4* p10 = reinterpret_cast<const float4*>(vnear + (size_t)(y1*WW+x0)*HD);
        const float4* p11 = reinterpret_cast<const float4*>(vnear + (size_t)(y1*WW+x1)*HD);

        float xin[HD+2];
        #pragma unroll
        for (int d4=0;d4<4;d4++){
            float4 a = p00[d4], bq = p01[d4], cq = p10[d4], dq = p11[d4];
            xin[4*d4  ] = a.x*w00 + bq.x*w01 + cq.x*w10 + dq.x*w11;
            xin[4*d4+1] = a.y*w00 + bq.y*w01 + cq.y*w10 + dq.y*w11;
            xin[4*d4+2] = a.z*w00 + bq.z*w01 + cq.z*w10 + dq.z*w11;
            xin[4*d4+3] = a.w*w00 + bq.w*w01 + cq.w*w10 + dq.w*w11;
        }
        xin[HD]=p0x; xin[HD+1]=p0y;

        #pragma unroll
        for (int k=0;k<HD+2;k++){
            float hh = tf32r(xin[k]);
            bhb[k*BPITCH+lane] = hh;
            blb[k*BPITCH+lane] = tf32r(xin[k]-hh);
        }
        __syncwarp();

        float crz[2][4][4], cgi[4][4], cgh[4][4];
        #pragma unroll
        for (int mt=0;mt<2;mt++)
            #pragma unroll
            for (int nt=0;nt<4;nt++)
                #pragma unroll
                for (int r2=0;r2<4;r2++) crz[mt][nt][r2]=0.f;
        #pragma unroll
        for (int nt=0;nt<4;nt++)
            #pragma unroll
            for (int r2=0;r2<4;r2++){ cgi[nt][r2]=0.f; cgh[nt][r2]=0.f; }

        #pragma unroll
        for (int kt=0; kt<5; kt++){
            float ah[3][4], al[3][4];
            #pragma unroll
            for (int mt=0; mt<3; mt++){
                int tt = kt*3+mt;
                float4 vh = *reinterpret_cast<const float4*>(&aF_h[(tt*32+lane)*4]);
                float4 vl = *reinterpret_cast<const float4*>(&aF_l[(tt*32+lane)*4]);
                ah[mt][0]=vh.x; ah[mt][1]=vh.y; ah[mt][2]=vh.z; ah[mt][3]=vh.w;
                al[mt][0]=vl.x; al[mt][1]=vl.y; al[mt][2]=vl.z; al[mt][3]=vl.w;
            }
            float bhf[4][2], blf[4][2];
            #pragma unroll
            for (int nt=0; nt<4; nt++){
                int c0 = (kt*8+t4)*BPITCH + nt*8 + g;
                int c1 = (kt*8+t4+4)*BPITCH + nt*8 + g;
                bhf[nt][0]=bhb[c0]; bhf[nt][1]=bhb[c1];
                blf[nt][0]=blb[c0]; blf[nt][1]=blb[c1];
            }
            #pragma unroll
            for (int nt=0; nt<4; nt++){
                mma8(crz[0][nt], ah[0], blf[nt]); mma8(crz[0][nt], al[0], bhf[nt]); mma8(crz[0][nt], ah[0], bhf[nt]);
                mma8(crz[1][nt], ah[1], blf[nt]); mma8(crz[1][nt], al[1], bhf[nt]); mma8(crz[1][nt], ah[1], bhf[nt]);
                if (kt < 3){
                    mma8(cgi[nt], ah[2], blf[nt]); mma8(cgi[nt], al[2], bhf[nt]); mma8(cgi[nt], ah[2], bhf[nt]);
                } else {
                    mma8(cgh[nt], ah[2], blf[nt]); mma8(cgh[nt], al[2], bhf[nt]); mma8(cgh[nt], ah[2], bhf[nt]);
                }
            }
        }

        #pragma unroll
        for (int nt=0; nt<4; nt++)
            #pragma unroll
            for (int idx=0; idx<4; idx++){
                int row = g + ((idx>>1)<<3);
                float rv = fsig(crz[0][nt][idx] + s_bsum[row]);
                float zv = fsig(crz[1][nt][idx] + s_bsum[16+row]);
                float hv = ftanh(cgi[nt][idx] + s_bihn[row] + rv*(cgh[nt][idx] + s_bhhn[row]));
                net_c[nt][idx] = (1.f-zv)*hv + zv*net_c[nt][idx];
            }
        __syncwarp();
        #pragma unroll
        for (int nt=0; nt<4; nt++)
            #pragma unroll
            for (int idx=0; idx<4; idx++){
                int row = g + ((idx>>1)<<3);
                int col = nt*8 + 2*t4 + (idx&1);
                float v = net_c[nt][idx];
                s_nw[row*BPITCH+col] = v;
                float hh = tf32r(v);
                bhb[(24+row)*BPITCH+col] = hh;
                blb[(24+row)*BPITCH+col] = tf32r(v-hh);
            }
        __syncwarp();

        float nloc[HD];
        #pragma unroll
        for (int d=0;d<HD;d++) nloc[d] = s_nw[d*BPITCH+lane];
        #pragma unroll
        for (int p=0;p<PP;p++){
            float d0 = s_offb[2*p], d1 = s_offb[2*p+1], da = s_ab[p];
            #pragma unroll
            for (int d=0;d<HD;d++){
                d0 += nloc[d]*s_offw[(2*p)*HD+d];
                d1 += nloc[d]*s_offw[(2*p+1)*HD+d];
                da += nloc[d]*s_aw[p*HD+d];
            }
            offs[2*p]+=d0; offs[2*p+1]+=d1; attn[p]+=da;
        }
    }

    float lg[NN*PP];
    float m = -1e30f;
    #pragma unroll
    for (int n=0;n<NN;n++){
        float tbv = g_tbias[bh_*NN+n];
        #pragma unroll
        for (int p=0;p<PP;p++){ float v2 = attn[p]+tbv; lg[n*PP+p]=v2; m = fmaxf(m,v2); }
    }
    float ssum = 0.f;
    #pragma unroll
    for (int i=0;i<NN*PP;i++){ lg[i]=__expf(lg[i]-m); ssum += lg[i]; }
    float inv = fdividef(1.f, ssum);
    float ent = 0.f;
    #pragma unroll
    for (int i=0;i<NN*PP;i++){ lg[i]*=inv; ent -= lg[i]*__logf(lg[i]+1e-8f); }
    g_ent[(size_t)bh_*HWSZ + pix] = ent;

    float acc[HD];
    #pragma unroll
    for (int d=0;d<HD;d++) acc[d]=0.f;
    #pragma unroll
    for (int p=0;p<PP;p++){
        float sgx = fminf(fmaxf(bx+offs[2*p],-1.f),1.f);
        float sgy = fminf(fmaxf(by+offs[2*p+1],-1.f),1.f);
        float ixf = (sgx+1.f)*0.5f*(WW-1);
        float iyf = (sgy+1.f)*0.5f*(HH-1);
        float x0f = floorf(ixf), y0f = floorf(iyf);
        float wx = ixf-x0f, wy = iyf-y0f;
        int x0 = min(max((int)x0f,0),WW-1);
        int x1 = min(max((int)x0f+1,0),WW-1);
        int y0 = min(max((int)y0f,0),HH-1);
        int y1 = min(max((int)y0f+1,0),HH-1);
        size_t o00=(size_t)(y0*WW+x0)*HD, o01=(size_t)(y0*WW+x1)*HD;
        size_t o10=(size_t)(y1*WW+x0)*HD, o11=(size_t)(y1*WW+x1)*HD;
        float w00=(1.f-wx)*(1.f-wy), w01=wx*(1.f-wy), w10=(1.f-wx)*wy, w11=wx*wy;
        #pragma unroll
        for (int n=0;n<NN;n++){
            float wnp = lg[n*PP+p];
            const float* vb2 = g_vp + ((size_t)(b*NN+n)*HEADS + h)*HWSZ*HD;
            const float4* a0 = reinterpret_cast<const float4*>(vb2 + o00);
            const float4* a1 = reinterpret_cast<const float4*>(vb2 + o01);
            const float4* a2 = reinterpret_cast<const float4*>(vb2 + o10);
            const float4* a3 = reinterpret_cast<const float4*>(vb2 + o11);
            #pragma unroll
            for (int d4=0;d4<4;d4++){
                float4 aa = a0[d4], bb = a1[d4], cc = a2[d4], dd = a3[d4];
                acc[4*d4  ] += wnp*(aa.x*w00 + bb.x*w01 + cc.x*w10 + dd.x*w11);
                acc[4*d4+1] += wnp*(aa.y*w00 + bb.y*w01 + cc.y*w10 + dd.y*w11);
                acc[4*d4+2] += wnp*(aa.z*w00 + bb.z*w01 + cc.z*w10 + dd.z*w11);
                acc[4*d4+3] += wnp*(aa.w*w00 + bb.w*w01 + cc.w*w10 + dd.w*w11);
            }
        }
    }
    float* op = g_agg + ((size_t)b*CCH + h*HD)*HWSZ + pix;
    #pragma unroll
    for (int d=0;d<HD;d++) op[(size_t)d*HWSZ] = acc[d];
}

// ---------------- entropy mean + confidence ----------------
__global__ void ent_k(float* __restrict__ out)
{
    int i = blockIdx.x*blockDim.x + threadIdx.x;
    if (i >= BB*HWSZ) return;
    int b = i / HWSZ, pix = i % HWSZ;
    float s = 0.f;
    #pragma unroll
    for (int h=0;h<HEADS;h++) s += g_ent[(size_t)(b*HEADS+h)*HWSZ + pix];
    s *= (1.0f/HEADS);
    float conf = 1.f - fminf(fmaxf(s/(2.7725887222397811f+1e-8f),0.f),1.f);
    out[(size_t)BB*CCH*HWSZ + i] = conf;
    out[(size_t)BB*CCH*HWSZ + BB*HWSZ + i] = s;
}

// ---------------- launch ----------------
extern "C" void kernel_launch(void* const* d_in, const int* in_sizes, int n_in,
                              void* d_out, int out_size)
{
    const float* query    = (const float*)d_in[0];
    const float* values   = (const float*)d_in[1];
    const float* rel_time = (const float*)d_in[2];
    const float* time_enc = (const float*)d_in[3];
    const float* qw  = (const float*)d_in[4];
    const float* qb  = (const float*)d_in[5];
    const float* vw  = (const float*)d_in[6];
    const float* vb  = (const float*)d_in[7];
    const float* dww = (const float*)d_in[8];
    const float* dwb = (const float*)d_in[9];
    const float* pww = (const float*)d_in[10];
    const float* pwb = (const float*)d_in[11];
    const float* wih = (const float*)d_in[12];
    const float* whh = (const float*)d_in[13];
    const float* bih = (const float*)d_in[14];
    const float* bhh = (const float*)d_in[15];
    const float* offw= (const float*)d_in[16];
    const float* offb= (const float*)d_in[17];
    const float* aw  = (const float*)d_in[18];
    const float* ab  = (const float*)d_in[19];
    const float* tw  = (const float*)d_in[20];
    const float* tb  = (const float*)d_in[21];
    const float* o1w = (const float*)d_in[22];
    const float* o1b = (const float*)d_in[23];
    const float* o2w = (const float*)d_in[24];
    const float* o2b = (const float*)d_in[25];
    const float* gate= (const float*)d_in[26];
    float* out = (float*)d_out;

    float *p_q, *p_v, *p_tmp, *p_net, *p_agg, *p_wprep;
    cudaGetSymbolAddress((void**)&p_q,    g_q);
    cudaGetSymbolAddress((void**)&p_v,    g_v);
    cudaGetSymbolAddress((void**)&p_tmp,  g_tmp);
    cudaGetSymbolAddress((void**)&p_net,  g_net);
    cudaGetSymbolAddress((void**)&p_agg,  g_agg);
    cudaGetSymbolAddress((void**)&p_wprep,g_wprep);

    cudaFuncSetAttribute(fused_k, cudaFuncAttributeMaxDynamicSharedMemorySize,
                         FK_SMEM_FLOATS*4);

    small_k<<<1,128>>>(rel_time, time_enc, tw, tb);
    wprep_k<<<dim3(8,5),256>>>(qw, vw, pww, o1w, o2w);
    conv1x1_mma_k<<<dim3(HWSZ/128, BB),    256>>>(query,  p_wprep + 0*8*4096, qb,  p_q,   0, 0, nullptr);
    conv1x1_mma_k<<<dim3(HWSZ/128, BB*NN), 256>>>(values, p_wprep + 1*8*4096, vb,  p_v,   0, 0, nullptr);
    vt_k<<<dim3(HWSZ/128, BB*NN*HEADS), 256>>>();
    dw_k<<<dim3(3,3,BB*CCH), 256>>>(query, dww, dwb);
    conv1x1_mma_k<<<dim3(HWSZ/128, BB),    256>>>(p_tmp,  p_wprep + 2*8*4096, pwb, p_net, 0, 1, nullptr);
    fused_k<<<(BB*HEADS*HWSZ)/128, 128, FK_SMEM_FLOATS*4>>>(wih, whh, bih, bhh, offw, offb, aw, ab);
    conv1x1_mma_k<<<dim3(HWSZ/128, BB),    256>>>(p_agg,  p_wprep + 3*8*4096, o1b, p_tmp, 1, 0, nullptr);
    conv1x1_mma_k<<<dim3(HWSZ/128, BB),    256>>>(p_tmp,  p_wprep + 4*8*4096, o2b, out,   2, 0, gate);
    ent_k<<<(BB*HWSZ)/128, 128>>>(out);
}

// round 17
// speedup vs baseline: 1.1164x; 1.1164x over previous
#include <cuda_runtime.h>
#include <math.h>
#include <stdint.h>

#define BB 2
#define NN 4
#define CCH 128
#define HEADS 8
#define PP 4
#define HH 96
#define WW 96
#define TCC 64
#define NITERS 3
#define HD 16
#define HWSZ (HH*WW)   // 9216
#define BPITCH 40

// ---------------- scratch (device globals; no allocation) ----------------
__device__ float g_q   [BB*CCH*HWSZ];          // BCHW
__device__ float g_v   [BB*NN*CCH*HWSZ];       // BCHW
__device__ float g_tmp [BB*CCH*HWSZ];          // BCHW
__device__ float g_net [BB*HEADS*HWSZ*HD];     // pixel-head-major
__device__ float g_agg [BB*CCH*HWSZ];          // BCHW
__device__ float g_ent [BB*HEADS*HWSZ];
__device__ float g_tbias[BB*HEADS*NN];
__device__ int   g_nid [BB];
__device__ float g_wprep[5*8*4096];            // pre-split/permuted conv weights

__device__ __forceinline__ float geluf(float v){ return 0.5f*v*(1.0f+erff(v*0.70710678118654752f)); }
__device__ __forceinline__ float sigm(float v){ return 1.0f/(1.0f+expf(-v)); }
__device__ __forceinline__ float tf32r(float x){
    uint32_t o; asm("cvt.rna.tf32.f32 %0, %1;" : "=r"(o) : "f"(x));
    return __uint_as_float(o);
}
__device__ __forceinline__ void mma8(float* c, const float* a, const float* b){
    asm volatile("mma.sync.aligned.m16n8k8.row.col.f32.tf32.tf32.f32 "
        "{%0,%1,%2,%3}, {%4,%5,%6,%7}, {%8,%9}, {%0,%1,%2,%3};"
        : "+f"(c[0]),"+f"(c[1]),"+f"(c[2]),"+f"(c[3])
        : "r"(__float_as_uint(a[0])),"r"(__float_as_uint(a[1])),
          "r"(__float_as_uint(a[2])),"r"(__float_as_uint(a[3])),
          "r"(__float_as_uint(b[0])),"r"(__float_as_uint(b[1])));
}

// ---------------- weight prep: permute + hi/lo split, once ----------------
__global__ void wprep_k(const float* __restrict__ qw, const float* __restrict__ vw,
                        const float* __restrict__ pww, const float* __restrict__ o1w,
                        const float* __restrict__ o2w)
{
    const float* ws[5] = {qw, vw, pww, o1w, o2w};
    int ck = blockIdx.x;            // k-chunk 0..7
    int ci = blockIdx.y;            // conv id 0..4
    const float* w = ws[ci];
    int tid = threadIdx.x;
    int oc  = tid >> 1;
    int klb = (tid & 1) * 8;
    const float* wp = w + (size_t)oc * CCH + ck*16 + klb;
    float4 v0 = *reinterpret_cast<const float4*>(wp);
    float4 v1 = *reinterpret_cast<const float4*>(wp + 4);
    float vv[8] = {v0.x,v0.y,v0.z,v0.w,v1.x,v1.y,v1.z,v1.w};
    int mt = oc >> 4, og = oc & 15, gi = og & 7, half = og >> 3;
    float* dst = g_wprep + ((size_t)ci*8 + ck)*4096;
    #pragma unroll
    for (int j=0;j<8;j++){
        int kl = klb + j;
        int kc = kl >> 3, kk = kl & 7;
        int tt = kk & 3, khalf = kk >> 2;
        int idx = ((mt*2+kc)*32 + gi*4 + tt)*4 + (half + 2*khalf);
        float hi = tf32r(vv[j]);
        dst[idx]        = hi;
        dst[2048 + idx] = tf32r(vv[j] - hi);
    }
}

// ---------------- tiny kernel: t_bias + nearest_idx ----------------
__global__ void small_k(const float* __restrict__ rel_time,
                        const float* __restrict__ time_enc,
                        const float* __restrict__ tw,
                        const float* __restrict__ tb)
{
    int t = threadIdx.x;
    if (t < BB*HEADS*NN) {
        int n = t % NN; int h = (t/NN) % HEADS; int b = t/(NN*HEADS);
        float s = tb[h];
        for (int k=0;k<TCC;k++) s += time_enc[(b*NN+n)*TCC+k]*tw[h*TCC+k];
        g_tbias[t] = s;
    } else if (t < BB*HEADS*NN + BB) {
        int b = t - BB*HEADS*NN;
        float best = fabsf(rel_time[b*NN]); int id = 0;
        for (int n=1;n<NN;n++){ float v=fabsf(rel_time[b*NN+n]); if (v<best){best=v;id=n;} }
        g_nid[b] = id;
    }
}

// ---------------- depthwise 7x7 + bias + gelu (smem tiled, sliding-window) ----------------
// 4 consecutive output rows per thread share a 10x7 input slab: 70 LDS instead of 196.
__global__ __launch_bounds__(256)
void dw_k(const float* __restrict__ q,
          const float* __restrict__ dww,
          const float* __restrict__ dwb)
{
    __shared__ float tile[38][40];
    __shared__ float wsm[49];
    int plane = blockIdx.z;            // b*CCH + c
    int c = plane & (CCH-1);
    int tx0 = blockIdx.x * 32;
    int ty0 = blockIdx.y * 32;
    const float* qp = q + (size_t)plane * HWSZ;
    int tid = threadIdx.x;
    if (tid < 49) wsm[tid] = dww[c*49 + tid];
    for (int i = tid; i < 38*38; i += 256){
        int r = i / 38, cc = i - r*38;
        int gy = ty0 + r - 3, gx = tx0 + cc - 3;
        float v = 0.f;
        if (gy>=0 && gy<HH && gx>=0 && gx<WW) v = qp[gy*WW+gx];
        tile[r][cc] = v;
    }
    __syncthreads();
    float wr[49];
    #pragma unroll
    for (int i=0;i<49;i++) wr[i]=wsm[i];
    int lx  = tid & 31;
    int ly0 = (tid >> 5) * 4;          // 8 warps x 4 consecutive rows = 32 rows
    float bz = dwb[c];
    float acc[4] = {0.f, 0.f, 0.f, 0.f};
    #pragma unroll
    for (int r = 0; r < 10; r++){
        float vals[7];
        #pragma unroll
        for (int kx=0;kx<7;kx++) vals[kx] = tile[ly0 + r][lx + kx];
        #pragma unroll
        for (int j=0;j<4;j++){
            int ky = r - j;
            if (ky >= 0 && ky < 7){
                #pragma unroll
                for (int kx=0;kx<7;kx++) acc[j] += vals[kx]*wr[ky*7+kx];
            }
        }
    }
    float* outp = g_tmp + (size_t)plane*HWSZ;
    #pragma unroll
    for (int j=0;j<4;j++)
        outp[(ty0+ly0+j)*WW + tx0+lx] = geluf(acc[j] + bz);
}

// ---------------- 3xTF32 tensor-core conv1x1 (R8-exact) ----------------
__global__ __launch_bounds__(256, 2)
void conv1x1_mma_k(const float* __restrict__ in, const float* __restrict__ wA,
                   const float* __restrict__ bias, float* __restrict__ out,
                   int act, int layout, const float* __restrict__ gate)
{
    __shared__ float sA[4096];           // [hi2048 | lo2048] permuted W chunk
    __shared__ float sB[2][16*132];      // hi/lo [k16][pix128 + pad4]
    const int tid  = threadIdx.x;
    const int lane = tid & 31;
    const int warp = tid >> 5;
    const int g  = lane >> 2;
    const int t4 = lane & 3;

    const int pix0 = blockIdx.x * 128;
    const int img  = blockIdx.y;
    const float* inb = in + (size_t)img * CCH * HWSZ;

    const int wOc  = (warp & 1) * 64;
    const int wPix = (warp >> 1) * 32;

    float c[4][4][4];
    #pragma unroll
    for (int i=0;i<4;i++)
        #pragma unroll
        for (int j=0;j<4;j++)
            #pragma unroll
            for (int r=0;r<4;r++) c[i][j][r]=0.f;

    for (int k0 = 0; k0 < CCH; k0 += 16) {
        {
            const float4* src = reinterpret_cast<const float4*>(wA + (size_t)(k0>>4)*4096);
            float4* dA = reinterpret_cast<float4*>(sA);
            dA[tid]       = src[tid];
            dA[tid + 256] = src[tid + 256];
            dA[tid + 512] = src[tid + 512];
            dA[tid + 768] = src[tid + 768];
        }
        {
            int kl = tid >> 4;
            int px = (tid & 15) * 8;
            const float* ip = inb + (size_t)(k0+kl)*HWSZ + pix0 + px;
            float4 v0 = *reinterpret_cast<const float4*>(ip);
            float4 v1 = *reinterpret_cast<const float4*>(ip+4);
            float vv[8] = {v0.x,v0.y,v0.z,v0.w,v1.x,v1.y,v1.z,v1.w};
            int base = kl*132 + px;
            #pragma unroll
            for (int j=0;j<8;j++){
                float hi = tf32r(vv[j]);
                sB[0][base+j] = hi;
                sB[1][base+j] = tf32r(vv[j] - hi);
            }
        }
        __syncthreads();
        #pragma unroll
        for (int kc=0; kc<2; kc++){
            float ah[4][4], al[4][4];
            #pragma unroll
            for (int mt=0; mt<4; mt++){
                int mtg = (wOc>>4) + mt;
                int idx = ((mtg*2+kc)*32+lane)*4;
                float4 avh = *reinterpret_cast<const float4*>(&sA[idx]);
                float4 avl = *reinterpret_cast<const float4*>(&sA[2048+idx]);
                ah[mt][0]=avh.x; ah[mt][1]=avh.y; ah[mt][2]=avh.z; ah[mt][3]=avh.w;
                al[mt][0]=avl.x; al[mt][1]=avl.y; al[mt][2]=avl.z; al[mt][3]=avl.w;
            }
            float bh[4][2], bl[4][2];
            #pragma unroll
            for (int nt=0; nt<4; nt++){
                int px = wPix + nt*8 + g;
                int i0 = (kc*8+t4)*132 + px;
                int i1 = (kc*8+t4+4)*132 + px;
                bh[nt][0] = sB[0][i0];  bh[nt][1] = sB[0][i1];
                bl[nt][0] = sB[1][i0];  bl[nt][1] = sB[1][i1];
            }
            #pragma unroll
            for (int mt=0; mt<4; mt++)
                #pragma unroll
                for (int nt=0; nt<4; nt++){
                    mma8(c[mt][nt], ah[mt], bl[nt]);
                    mma8(c[mt][nt], al[mt], bh[nt]);
                    mma8(c[mt][nt], ah[mt], bh[nt]);
                }
        }
        __syncthreads();
    }

    #pragma unroll
    for (int mt=0; mt<4; mt++){
        int oc1 = wOc + mt*16 + g;
        int oc2 = oc1 + 8;
        float b1 = bias[oc1], b2 = bias[oc2];
        float m1 = 1.f, m2 = 1.f;
        if (act==2){ m1 = sigm(gate[oc1]); m2 = sigm(gate[oc2]); }
        #pragma unroll
        for (int nt=0; nt<4; nt++){
            int p = pix0 + wPix + nt*8 + t4*2;
            float v0 = c[mt][nt][0] + b1, v1 = c[mt][nt][1] + b1;
            float v2 = c[mt][nt][2] + b2, v3 = c[mt][nt][3] + b2;
            if (act==1){ v0=geluf(v0); v1=geluf(v1); v2=geluf(v2); v3=geluf(v3); }
            else if (act==2){ v0*=m1; v1*=m1; v2*=m2; v3*=m2; }
            if (layout==0){
                float2* o1 = reinterpret_cast<float2*>(out + (size_t)img*CCH*HWSZ + (size_t)oc1*HWSZ + p);
                float2* o2 = reinterpret_cast<float2*>(out + (size_t)img*CCH*HWSZ + (size_t)oc2*HWSZ + p);
                *o1 = make_float2(v0, v1);
                *o2 = make_float2(v2, v3);
            } else {
                out[(((size_t)img*HEADS + (oc1>>4))*HWSZ + p  )*HD + (oc1&15)] = v0;
                out[(((size_t)img*HEADS + (oc1>>4))*HWSZ + p+1)*HD + (oc1&15)] = v1;
                out[(((size_t)img*HEADS + (oc2>>4))*HWSZ + p  )*HD + (oc2&15)] = v2;
                out[(((size_t)img*HEADS + (oc2>>4))*HWSZ + p+1)*HD + (oc2&15)] = v3;
            }
        }
    }
}

// ---------------- fused: correlation + MMA-GRU + softmax + final gather (R8-exact) ----------------
#define FK_SMEM_FLOATS 21104
__global__ __launch_bounds__(128)
void fused_k(const float* __restrict__ wih, const float* __restrict__ whh,
             const float* __restrict__ bih, const float* __restrict__ bhh,
             const float* __restrict__ offw, const float* __restrict__ offb,
             const float* __restrict__ aw,  const float* __restrict__ ab)
{
    extern __shared__ float sm[];
    float* s_wih = sm;
    float* s_whh = sm+864;
    float* s_bsum= sm+1632;
    float* s_bihn= sm+1664;
    float* s_bhhn= sm+1680;
    float* s_offw= sm+1696;
    float* s_aw  = sm+1824;
    float* s_offb= sm+1888;
    float* s_ab  = sm+1896;
    float* aF_h  = sm+1904;
    float* aF_l  = sm+3824;
    float* s_bhA = sm+5744;
    float* s_blA = sm+12144;
    float* s_nA  = sm+18544;

    int t = threadIdx.x;
    int lane = t & 31, warp = t >> 5;
    int g = lane >> 2, t4 = lane & 3;

    for (int i=t;i<864;i+=128) s_wih[i]=wih[i];
    for (int i=t;i<768;i+=128) s_whh[i]=whh[i];
    if (t<32) s_bsum[t]=bih[t]+bhh[t];
    else if (t<48){ s_bihn[t-32]=bih[t]; s_bhhn[t-32]=bhh[t]; }
    s_offw[t] = offw[t];
    if (t<64) s_aw[t] = aw[t];
    if (t>=64 && t<72) s_offb[t-64]=offb[t-64];
    if (t>=72 && t<76) s_ab[t-72]=ab[t-72];
    __syncthreads();

    for (int tt=warp; tt<15; tt+=4){
        int kt = tt/3, mt = tt - kt*3;
        #pragma unroll
        for (int idx=0; idx<4; idx++){
            int row = g + ((idx & 1) << 3);
            int col = kt*8 + t4 + ((idx >> 1) << 2);
            float e;
            if (mt < 2){
                int j = mt*16 + row;
                e = (col < 18) ? s_wih[j*18+col] : ((col < 24) ? 0.f : s_whh[j*16 + col-24]);
            } else if (kt < 3){
                e = (col < 18) ? s_wih[(32+row)*18 + col] : 0.f;
            } else {
                e = s_whh[(32+row)*16 + (col-24)];
            }
            float h = tf32r(e);
            aF_h[(tt*32+lane)*4+idx] = h;
            aF_l[(tt*32+lane)*4+idx] = tf32r(e - h);
        }
    }

    float* bhb = s_bhA + warp*1600;
    float* blb = s_blA + warp*1600;
    float* s_nw = s_nA + warp*640;
    for (int i=lane; i<6*BPITCH; i+=32){ bhb[18*BPITCH+i]=0.f; blb[18*BPITCH+i]=0.f; }
    __syncthreads();

    int ph  = blockIdx.x*128 + t;
    int pix = ph % HWSZ;
    int bh_ = ph / HWSZ;
    int h   = bh_ % HEADS;
    int b   = bh_ / HEADS;
    int x   = pix % WW, y = pix / WW;
    float bx = -1.f + x*(2.f/(WW-1));
    float by = -1.f + y*(2.f/(HH-1));

    const float* vnear = g_v + ((size_t)(b*NN + g_nid[b])*CCH + h*HD)*HWSZ;
    const float* qbase = g_q + ((size_t)b*CCH + h*HD)*HWSZ + pix;

    float qv[HD];
    #pragma unroll
    for (int d=0;d<HD;d++) qv[d] = qbase[(size_t)d*HWSZ];
    const int sdx[5] = {0,-1,1,0,0};
    const int sdy[5] = {0,0,0,-1,1};
    float bestsc = 0.f; int bi = 0;
    #pragma unroll
    for (int s=0;s<5;s++){
        int sy = y - sdy[s], sx = x - sdx[s];
        float sc = 0.f;
        if (sy>=0 && sy<HH && sx>=0 && sx<WW){
            int sp = sy*WW+sx;
            #pragma unroll
            for (int d=0;d<HD;d++) sc += qv[d]*vnear[(size_t)d*HWSZ + sp];
        }
        if (s==0 || sc > bestsc){ bestsc = sc; bi = s; }
    }
    float ox0 = sdy[bi]*(2.f/WW);
    float oy0 = sdx[bi]*(2.f/HH);

    float offs[PP*2];
    #pragma unroll
    for (int p=0;p<PP;p++){ offs[2*p]=ox0; offs[2*p+1]=oy0; }
    float attn[PP] = {0.f,0.f,0.f,0.f};

    {
        const float4* np4 = reinterpret_cast<const float4*>(g_net + (size_t)ph*HD);
        #pragma unroll
        for (int d4=0; d4<4; d4++){
            float4 v = np4[d4];
            float vv[4] = {v.x,v.y,v.z,v.w};
            #pragma unroll
            for (int j=0;j<4;j++){
                int d = d4*4+j;
                s_nw[d*BPITCH+lane] = vv[j];
                float hh = tf32r(vv[j]);
                bhb[(24+d)*BPITCH+lane] = hh;
                blb[(24+d)*BPITCH+lane] = tf32r(vv[j]-hh);
            }
        }
    }
    __syncwarp();
    float net_c[4][4];
    #pragma unroll
    for (int nt=0; nt<4; nt++)
        #pragma unroll
        for (int idx=0; idx<4; idx++){
            int row = g + ((idx>>1)<<3);
            int col = nt*8 + 2*t4 + (idx&1);
            net_c[nt][idx] = s_nw[row*BPITCH+col];
        }

    for (int it=0; it<NITERS; it++){
        float p0x = offs[0], p0y = offs[1];
        float sgx = fminf(fmaxf(bx+p0x,-1.f),1.f);
        float sgy = fminf(fmaxf(by+p0y,-1.f),1.f);
        float ixf = (sgx+1.f)*0.5f*(WW-1);
        float iyf = (sgy+1.f)*0.5f*(HH-1);
        float x0f = floorf(ixf), y0f = floorf(iyf);
        float wx = ixf-x0f, wy = iyf-y0f;
        int x0 = min(max((int)x0f,0),WW-1);
        int x1 = min(max((int)x0f+1,0),WW-1);
        int y0 = min(max((int)y0f,0),HH-1);
        int y1 = min(max((int)y0f+1,0),HH-1);
        int i00=y0*WW+x0, i01=y0*WW+x1, i10=y1*WW+x0, i11=y1*WW+x1;
        float w00=(1.f-wx)*(1.f-wy), w01=wx*(1.f-wy), w10=(1.f-wx)*wy, w11=wx*wy;

        float xin[HD+2];
        #pragma unroll
        for (int d=0;d<HD;d++){
            const float* pl = vnear + (size_t)d*HWSZ;
            xin[d] = pl[i00]*w00 + pl[i01]*w01 + pl[i10]*w10 + pl[i11]*w11;
        }
        xin[HD]=p0x; xin[HD+1]=p0y;

        #pragma unroll
        for (int k=0;k<HD+2;k++){
            float hh = tf32r(xin[k]);
            bhb[k*BPITCH+lane] = hh;
            blb[k*BPITCH+lane] = tf32r(xin[k]-hh);
        }
        __syncwarp();

        float crz[2][4][4], cgi[4][4], cgh[4][4];
        #pragma unroll
        for (int mt=0;mt<2;mt++)
            #pragma unroll
            for (int nt=0;nt<4;nt++)
                #pragma unroll
                for (int r2=0;r2<4;r2++) crz[mt][nt][r2]=0.f;
        #pragma unroll
        for (int nt=0;nt<4;nt++)
            #pragma unroll
            for (int r2=0;r2<4;r2++){ cgi[nt][r2]=0.f; cgh[nt][r2]=0.f; }

        #pragma unroll
        for (int kt=0; kt<5; kt++){
            float ah[3][4], al[3][4];
            #pragma unroll
            for (int mt=0; mt<3; mt++){
                int tt = kt*3+mt;
                float4 vh = *reinterpret_cast<const float4*>(&aF_h[(tt*32+lane)*4]);
                float4 vl = *reinterpret_cast<const float4*>(&aF_l[(tt*32+lane)*4]);
                ah[mt][0]=vh.x; ah[mt][1]=vh.y; ah[mt][2]=vh.z; ah[mt][3]=vh.w;
                al[mt][0]=vl.x; al[mt][1]=vl.y; al[mt][2]=vl.z; al[mt][3]=vl.w;
            }
            float bhf[4][2], blf[4][2];
            #pragma unroll
            for (int nt=0; nt<4; nt++){
                int c0 = (kt*8+t4)*BPITCH + nt*8 + g;
                int c1 = (kt*8+t4+4)*BPITCH + nt*8 + g;
                bhf[nt][0]=bhb[c0]; bhf[nt][1]=bhb[c1];
                blf[nt][0]=blb[c0]; blf[nt][1]=blb[c1];
            }
            #pragma unroll
            for (int nt=0; nt<4; nt++){
                mma8(crz[0][nt], ah[0], blf[nt]); mma8(crz[0][nt], al[0], bhf[nt]); mma8(crz[0][nt], ah[0], bhf[nt]);
                mma8(crz[1][nt], ah[1], blf[nt]); mma8(crz[1][nt], al[1], bhf[nt]); mma8(crz[1][nt], ah[1], bhf[nt]);
                if (kt < 3){
                    mma8(cgi[nt], ah[2], blf[nt]); mma8(cgi[nt], al[2], bhf[nt]); mma8(cgi[nt], ah[2], bhf[nt]);
                } else {
                    mma8(cgh[nt], ah[2], blf[nt]); mma8(cgh[nt], al[2], bhf[nt]); mma8(cgh[nt], ah[2], bhf[nt]);
                }
            }
        }

        #pragma unroll
        for (int nt=0; nt<4; nt++)
            #pragma unroll
            for (int idx=0; idx<4; idx++){
                int row = g + ((idx>>1)<<3);
                float rv = sigm(crz[0][nt][idx] + s_bsum[row]);
                float zv = sigm(crz[1][nt][idx] + s_bsum[16+row]);
                float hv = tanhf(cgi[nt][idx] + s_bihn[row] + rv*(cgh[nt][idx] + s_bhhn[row]));
                net_c[nt][idx] = (1.f-zv)*hv + zv*net_c[nt][idx];
            }
        __syncwarp();
        #pragma unroll
        for (int nt=0; nt<4; nt++)
            #pragma unroll
            for (int idx=0; idx<4; idx++){
                int row = g + ((idx>>1)<<3);
                int col = nt*8 + 2*t4 + (idx&1);
                float v = net_c[nt][idx];
                s_nw[row*BPITCH+col] = v;
                float hh = tf32r(v);
                bhb[(24+row)*BPITCH+col] = hh;
                blb[(24+row)*BPITCH+col] = tf32r(v-hh);
            }
        __syncwarp();

        float nloc[HD];
        #pragma unroll
        for (int d=0;d<HD;d++) nloc[d] = s_nw[d*BPITCH+lane];
        #pragma unroll
        for (int p=0;p<PP;p++){
            float d0 = s_offb[2*p], d1 = s_offb[2*p+1], da = s_ab[p];
            #pragma unroll
            for (int d=0;d<HD;d++){
                d0 += nloc[d]*s_offw[(2*p)*HD+d];
                d1 += nloc[d]*s_offw[(2*p+1)*HD+d];
                da += nloc[d]*s_aw[p*HD+d];
            }
            offs[2*p]+=d0; offs[2*p+1]+=d1; attn[p]+=da;
        }
    }

    float lg[NN*PP];
    float m = -1e30f;
    #pragma unroll
    for (int n=0;n<NN;n++){
        float tbv = g_tbias[bh_*NN+n];
        #pragma unroll
        for (int p=0;p<PP;p++){ float v2 = attn[p]+tbv; lg[n*PP+p]=v2; m = fmaxf(m,v2); }
    }
    float ssum = 0.f;
    #pragma unroll
    for (int i=0;i<NN*PP;i++){ lg[i]=expf(lg[i]-m); ssum += lg[i]; }
    float inv = 1.f/ssum;
    float ent = 0.f;
    #pragma unroll
    for (int i=0;i<NN*PP;i++){ lg[i]*=inv; ent -= lg[i]*logf(lg[i]+1e-8f); }
    g_ent[(size_t)bh_*HWSZ + pix] = ent;

    float acc[HD];
    #pragma unroll
    for (int d=0;d<HD;d++) acc[d]=0.f;
    #pragma unroll
    for (int p=0;p<PP;p++){
        float sgx = fminf(fmaxf(bx+offs[2*p],-1.f),1.f);
        float sgy = fminf(fmaxf(by+offs[2*p+1],-1.f),1.f);
        float ixf = (sgx+1.f)*0.5f*(WW-1);
        float iyf = (sgy+1.f)*0.5f*(HH-1);
        float x0f = floorf(ixf), y0f = floorf(iyf);
        float wx = ixf-x0f, wy = iyf-y0f;
        int x0 = min(max((int)x0f,0),WW-1);
        int x1 = min(max((int)x0f+1,0),WW-1);
        int y0 = min(max((int)y0f,0),HH-1);
        int y1 = min(max((int)y0f+1,0),HH-1);
        int i00=y0*WW+x0, i01=y0*WW+x1, i10=y1*WW+x0, i11=y1*WW+x1;
        float w00=(1.f-wx)*(1.f-wy), w01=wx*(1.f-wy), w10=(1.f-wx)*wy, w11=wx*wy;
        #pragma unroll
        for (int n=0;n<NN;n++){
            float wnp = lg[n*PP+p];
            const float* vb2 = g_v + ((size_t)(b*NN+n)*CCH + h*HD)*HWSZ;
            #pragma unroll
            for (int d=0;d<HD;d++){
                const float* pl = vb2 + (size_t)d*HWSZ;
                acc[d] += wnp*(pl[i00]*w00 + pl[i01]*w01 + pl[i10]*w10 + pl[i11]*w11);
            }
        }
    }
    float* op = g_agg + ((size_t)b*CCH + h*HD)*HWSZ + pix;
    #pragma unroll
    for (int d=0;d<HD;d++) op[(size_t)d*HWSZ] = acc[d];
}

// ---------------- entropy mean + confidence ----------------
__global__ void ent_k(float* __restrict__ out)
{
    int i = blockIdx.x*blockDim.x + threadIdx.x;
    if (i >= BB*HWSZ) return;
    int b = i / HWSZ, pix = i % HWSZ;
    float s = 0.f;
    #pragma unroll
    for (int h=0;h<HEADS;h++) s += g_ent[(size_t)(b*HEADS+h)*HWSZ + pix];
    s *= (1.0f/HEADS);
    float conf = 1.f - fminf(fmaxf(s/(2.7725887222397811f+1e-8f),0.f),1.f);
    out[(size_t)BB*CCH*HWSZ + i] = conf;
    out[(size_t)BB*CCH*HWSZ + BB*HWSZ + i] = s;
}

// ---------------- launch ----------------
extern "C" void kernel_launch(void* const* d_in, const int* in_sizes, int n_in,
                              void* d_out, int out_size)
{
    const float* query    = (const float*)d_in[0];
    const float* values   = (const float*)d_in[1];
    const float* rel_time = (const float*)d_in[2];
    const float* time_enc = (const float*)d_in[3];
    const float* qw  = (const float*)d_in[4];
    const float* qb  = (const float*)d_in[5];
    const float* vw  = (const float*)d_in[6];
    const float* vb  = (const float*)d_in[7];
    const float* dww = (const float*)d_in[8];
    const float* dwb = (const float*)d_in[9];
    const float* pww = (const float*)d_in[10];
    const float* pwb = (const float*)d_in[11];
    const float* wih = (const float*)d_in[12];
    const float* whh = (const float*)d_in[13];
    const float* bih = (const float*)d_in[14];
    const float* bhh = (const float*)d_in[15];
    const float* offw= (const float*)d_in[16];
    const float* offb= (const float*)d_in[17];
    const float* aw  = (const float*)d_in[18];
    const float* ab  = (const float*)d_in[19];
    const float* tw  = (const float*)d_in[20];
    const float* tb  = (const float*)d_in[21];
    const float* o1w = (const float*)d_in[22];
    const float* o1b = (const float*)d_in[23];
    const float* o2w = (const float*)d_in[24];
    const float* o2b = (const float*)d_in[25];
    const float* gate= (const float*)d_in[26];
    float* out = (float*)d_out;

    float *p_q, *p_v, *p_tmp, *p_net, *p_agg, *p_wprep;
    cudaGetSymbolAddress((void**)&p_q,    g_q);
    cudaGetSymbolAddress((void**)&p_v,    g_v);
    cudaGetSymbolAddress((void**)&p_tmp,  g_tmp);
    cudaGetSymbolAddress((void**)&p_net,  g_net);
    cudaGetSymbolAddress((void**)&p_agg,  g_agg);
    cudaGetSymbolAddress((void**)&p_wprep,g_wprep);

    cudaFuncSetAttribute(fused_k, cudaFuncAttributeMaxDynamicSharedMemorySize,
                         FK_SMEM_FLOATS*4);

    small_k<<<1,128>>>(rel_time, time_enc, tw, tb);
    wprep_k<<<dim3(8,5),256>>>(qw, vw, pww, o1w, o2w);
    conv1x1_mma_k<<<dim3(HWSZ/128, BB),    256>>>(query,  p_wprep + 0*8*4096, qb,  p_q,   0, 0, nullptr);
    conv1x1_mma_k<<<dim3(HWSZ/128, BB*NN), 256>>>(values, p_wprep + 1*8*4096, vb,  p_v,   0, 0, nullptr);
    dw_k<<<dim3(3,3,BB*CCH), 256>>>(query, dww, dwb);
    conv1x1_mma_k<<<dim3(HWSZ/128, BB),    256>>>(p_tmp,  p_wprep + 2*8*4096, pwb, p_net, 0, 1, nullptr);
    fused_k<<<(BB*HEADS*HWSZ)/128, 128, FK_SMEM_FLOATS*4>>>(wih, whh, bih, bhh, offw, offb, aw, ab);
    conv1x1_mma_k<<<dim3(HWSZ/128, BB),    256>>>(p_agg,  p_wprep + 3*8*4096, o1b, p_tmp, 1, 0, nullptr);
    conv1x1_mma_k<<<dim3(HWSZ/128, BB),    256>>>(p_tmp,  p_wprep + 4*8*4096, o2b, out,   2, 0, gate);
    ent_k<<<(BB*HWSZ)/128, 128>>>(out);
}